// round 14
// baseline (speedup 1.0000x reference)
#include <cuda_runtime.h>
#include <stdint.h>
#include <math.h>

#define BB 32
#define NN 577
#define CC 768
#define HH 12
#define DD 64
#define MM (BB*NN)      // 18464
#define KDIM 768
#define QKV_N 2304

// ---------------- scratch ----------------
__device__ float g_q[BB*HH*NN*DD];   // [B,H,N,D]
__device__ float g_k[BB*HH*NN*DD];
__device__ float g_v[BB*HH*NN*DD];
__device__ float g_o[MM*CC];         // attention output (tf32-rounded), [B*N, C]
__device__ float g_xr[MM*KDIM];      // x, tf32-rounded
__device__ float g_wq[QKV_N*KDIM];   // qkv_w, tf32-rounded
__device__ float g_wp[CC*KDIM];      // proj_w, tf32-rounded
__device__ uint16_t g_kh[BB*HH*NN*DD], g_kl[BB*HH*NN*DD];   // K bf16 hi/lo (post-RoPE)
__device__ uint16_t g_vh[BB*HH*NN*DD], g_vl[BB*HH*NN*DD];   // V bf16 hi/lo

__device__ __forceinline__ float to_tf32(float x) {
    uint32_t u;
    asm("cvt.rna.tf32.f32 %0, %1;" : "=r"(u) : "f"(x));
    return __uint_as_float(u);
}

// bf16 helpers
__device__ __forceinline__ uint32_t f2bf(float x) {
    uint32_t u = __float_as_uint(x);
    return (u + 0x7FFFu + ((u >> 16) & 1u)) >> 16;
}
__device__ __forceinline__ float bf2f(uint32_t h) {
    return __uint_as_float(h << 16);
}
__device__ __forceinline__ uint32_t pack2(float a, float b) {
    return f2bf(a) | (f2bf(b) << 16);
}
__device__ __forceinline__ void split2(float a, float b, uint32_t& hi, uint32_t& lo) {
    uint32_t ha = f2bf(a), hb = f2bf(b);
    hi = ha | (hb << 16);
    lo = pack2(a - bf2f(ha), b - bf2f(hb));
}

__device__ __forceinline__ void mma_bf16(float* c, const uint32_t* a, uint32_t b0, uint32_t b1) {
    asm volatile(
        "mma.sync.aligned.m16n8k16.row.col.f32.bf16.bf16.f32 "
        "{%0,%1,%2,%3},{%4,%5,%6,%7},{%8,%9},{%0,%1,%2,%3};"
        : "+f"(c[0]), "+f"(c[1]), "+f"(c[2]), "+f"(c[3])
        : "r"(a[0]), "r"(a[1]), "r"(a[2]), "r"(a[3]), "r"(b0), "r"(b1));
}

__device__ __forceinline__ void ldsm4t(uint32_t& a, uint32_t& b, uint32_t& c, uint32_t& d,
                                       uint32_t addr) {
    asm volatile("ldmatrix.sync.aligned.m8n8.x4.trans.shared.b16 {%0,%1,%2,%3}, [%4];"
        : "=r"(a), "=r"(b), "=r"(c), "=r"(d) : "r"(addr));
}

__device__ __forceinline__ void ldsm4(uint32_t& a, uint32_t& b, uint32_t& c, uint32_t& d,
                                      uint32_t addr) {
    asm volatile("ldmatrix.sync.aligned.m8n8.x4.shared.b16 {%0,%1,%2,%3}, [%4];"
        : "=r"(a), "=r"(b), "=r"(c), "=r"(d) : "r"(addr));
}

__device__ __forceinline__ void cp16(uint32_t dst, const void* src, bool pred) {
    int sz = pred ? 16 : 0;
    asm volatile("cp.async.cg.shared.global [%0], [%1], 16, %2;"
                 :: "r"(dst), "l"(src), "r"(sz));
}

// ---------------- tf32 conversion (elementwise, float4) ----------------
__global__ void cvt_tf32_kernel(const float* __restrict__ in, float* __restrict__ out, int n4)
{
    int i = blockIdx.x * blockDim.x + threadIdx.x;
    if (i < n4) {
        float4 v = ((const float4*)in)[i];
        v.x = to_tf32(v.x); v.y = to_tf32(v.y);
        v.z = to_tf32(v.z); v.w = to_tf32(v.w);
        ((float4*)out)[i] = v;
    }
}

// ---------------- fp32 -> bf16 hi/lo split ----------------
__global__ void cvt_bf16_kernel(const float* __restrict__ in,
                                uint16_t* __restrict__ outh,
                                uint16_t* __restrict__ outl, int n4)
{
    int i = blockIdx.x * blockDim.x + threadIdx.x;
    if (i < n4) {
        float4 v = ((const float4*)in)[i];
        uint32_t h0, l0, h1, l1;
        split2(v.x, v.y, h0, l0);
        split2(v.z, v.w, h1, l1);
        ((uint2*)outh)[i] = make_uint2(h0, h1);
        ((uint2*)outl)[i] = make_uint2(l0, l1);
    }
}

// ---------------- tf32 GEMM, 2-stage cp.async (round-12, proven) ----------
#define GEMM_SMEM (4 * 128 * 32 * 4)   // 65536 B

template<int MODE>
__global__ __launch_bounds__(256) void mma_gemm(
    const float* __restrict__ Aop, const float* __restrict__ Wop,
    const float* __restrict__ bias_q, const float* __restrict__ bias_v,
    float* __restrict__ out)
{
    extern __shared__ float smg[];
    float* As = smg;                // [2][128*32]
    float* Bs = smg + 2*128*32;

    const int tid  = threadIdx.x;
    const int lane = tid & 31;
    const int warp = tid >> 5;
    const int wm   = (warp >> 2) * 64;
    const int wn   = (warp & 3) * 32;
    const int r    = lane >> 2;
    const int cg   = lane & 3;

    const int m0 = blockIdx.y * 128;
    const int n0 = blockIdx.x * 128;

    uint32_t asu = (uint32_t)__cvta_generic_to_shared(As);
    uint32_t bsu = (uint32_t)__cvta_generic_to_shared(Bs);

    const int srow = tid >> 3;
    const int sg   = tid & 7;

    float acc[4][4][4];
    #pragma unroll
    for (int i = 0; i < 4; i++)
        #pragma unroll
        for (int j = 0; j < 4; j++)
            #pragma unroll
            for (int q = 0; q < 4; q++) acc[i][j][q] = 0.f;

    const int NK = KDIM / 32;   // 24

    auto issue = [&](int kt, int s) {
        int k0 = kt * 32;
        #pragma unroll
        for (int i = 0; i < 4; i++) {
            int row = srow + 32*i;
            int sw  = ((sg ^ (row & 7)) << 2);
            uint32_t off = (uint32_t)((s*4096 + row*32 + sw) << 2);
            cp16(asu + off, &Aop[(size_t)(m0+row)*KDIM + k0 + sg*4], (m0+row) < MM);
            cp16(bsu + off, &Wop[(size_t)(n0+row)*KDIM + k0 + sg*4], true);
        }
        asm volatile("cp.async.commit_group;");
    };

    issue(0, 0);

    for (int kt = 0; kt < NK; kt++) {
        const int s = kt & 1;
        asm volatile("cp.async.wait_group 0;");
        __syncthreads();
        if (kt + 1 < NK) issue(kt + 1, s ^ 1);

        const float* Ab = As + s*4096;
        const float* Bb = Bs + s*4096;

        #pragma unroll
        for (int kk = 0; kk < 32; kk += 8) {
            const int g0 = kk >> 2;
            const int c0 = ((g0 ^ r) << 2) + cg;
            const int c1 = (((g0 + 1) ^ r) << 2) + cg;
            uint32_t af[4][4], bf[4][2];
            #pragma unroll
            for (int mt = 0; mt < 4; mt++) {
                const float* p = &Ab[(wm + mt*16 + r)*32];
                af[mt][0] = __float_as_uint(p[c0]);
                af[mt][1] = __float_as_uint(p[8*32 + c0]);
                af[mt][2] = __float_as_uint(p[c1]);
                af[mt][3] = __float_as_uint(p[8*32 + c1]);
            }
            #pragma unroll
            for (int nt = 0; nt < 4; nt++) {
                const float* p = &Bb[(wn + nt*8 + r)*32];
                bf[nt][0] = __float_as_uint(p[c0]);
                bf[nt][1] = __float_as_uint(p[c1]);
            }
            #pragma unroll
            for (int mt = 0; mt < 4; mt++)
                #pragma unroll
                for (int nt = 0; nt < 4; nt++) {
                    asm volatile(
                        "mma.sync.aligned.m16n8k8.row.col.f32.tf32.tf32.f32 "
                        "{%0,%1,%2,%3},{%4,%5,%6,%7},{%8,%9},{%0,%1,%2,%3};"
                        : "+f"(acc[mt][nt][0]), "+f"(acc[mt][nt][1]),
                          "+f"(acc[mt][nt][2]), "+f"(acc[mt][nt][3])
                        : "r"(af[mt][0]), "r"(af[mt][1]),
                          "r"(af[mt][2]), "r"(af[mt][3]),
                          "r"(bf[nt][0]), "r"(bf[nt][1]));
                }
        }
    }

    // ---------------- epilogue ----------------
    #pragma unroll
    for (int nt = 0; nt < 4; nt++) {
        int col = n0 + wn + nt*8 + 2*cg;
        if (MODE == 0) {
            int which = col / CC;
            int rem   = col - which*CC;
            int h     = rem >> 6;
            int d     = rem & 63;
            float b0 = (which == 0) ? bias_q[rem]   : (which == 2) ? bias_v[rem]   : 0.f;
            float b1 = (which == 0) ? bias_q[rem+1] : (which == 2) ? bias_v[rem+1] : 0.f;
            float* dst = (which == 0) ? g_q : (which == 1) ? g_k : g_v;
            #pragma unroll
            for (int mt = 0; mt < 4; mt++) {
                #pragma unroll
                for (int half = 0; half < 2; half++) {
                    int m = m0 + wm + mt*16 + r + half*8;
                    if (m < MM) {
                        int bb = m / NN, n = m - bb*NN;
                        float2 v = make_float2(acc[mt][nt][half*2]   + b0,
                                               acc[mt][nt][half*2+1] + b1);
                        *(float2*)&dst[(((size_t)bb*HH + h)*NN + n)*DD + d] = v;
                    }
                }
            }
        } else {
            float b0 = bias_q[col], b1 = bias_q[col+1];
            #pragma unroll
            for (int mt = 0; mt < 4; mt++) {
                #pragma unroll
                for (int half = 0; half < 2; half++) {
                    int m = m0 + wm + mt*16 + r + half*8;
                    if (m < MM) {
                        float2 v = make_float2(acc[mt][nt][half*2]   + b0,
                                               acc[mt][nt][half*2+1] + b1);
                        *(float2*)&out[(size_t)m*CC + col] = v;
                    }
                }
            }
        }
    }
}

// ---------------- RoPE ----------------
__global__ void rope_kernel(const float* __restrict__ rope)
{
    int idx = blockIdx.x * blockDim.x + threadIdx.x;
    const int total = BB*HH*(NN-1)*(DD/2);
    if (idx >= total) return;
    int pair = idx & 31;
    int rest = idx >> 5;
    int nr = rest % (NN-1);
    int bh = rest / (NN-1);
    int d0 = pair * 2;

    float s0 = rope[nr*2*DD + d0];
    float s1 = rope[nr*2*DD + d0 + 1];
    float c0 = rope[nr*2*DD + DD + d0];
    float c1 = rope[nr*2*DD + DD + d0 + 1];

    int base = (bh*NN + (nr + 1))*DD + d0;
    float2 q = *(float2*)&g_q[base];
    float2 k = *(float2*)&g_k[base];
    *(float2*)&g_q[base] = make_float2(q.x*c0 - q.y*s0, q.y*c1 + q.x*s1);
    *(float2*)&g_k[base] = make_float2(k.x*c0 - k.y*s0, k.y*c1 + k.x*s1);
}

// ---------------- Tensor-core flash attention v3 --------------------------
// K/V pre-split to bf16 hi/lo in global; staged via cp.async, double-buffered.
#define AT_STR 36                      // u32 row stride (144 B)
#define REGU   (64*AT_STR)             // u32 per region (Kh/Kl/Vh/Vl)
#define ATTN4_SMEM (2*4*REGU*4)        // 73728 B

__global__ __launch_bounds__(256) void attn_mma_kernel()
{
    extern __shared__ uint32_t smu[];
    const uint32_t smem_u = (uint32_t)__cvta_generic_to_shared(smu);

    const int tid  = threadIdx.x;
    const int lane = tid & 31;
    const int wid  = tid >> 5;
    const int r    = lane >> 2;
    const int cg   = lane & 3;

    const int bh   = blockIdx.y;
    const int q0   = blockIdx.x * 128;
    const int base = bh * NN * DD;
    const float scale = 0.125f;

    // trans-ldmatrix lane addressing (V)
    const int crow = ((lane >> 3) & 1) * 8 + (lane & 7);
    const int dcol = (lane >> 4) * 8;
    // non-trans ldmatrix lane addressing (K)
    const uint32_t lrow = (uint32_t)((((lane >> 4)*8 + (lane & 7)) * (AT_STR*4))
                                     + ((lane >> 3) & 1) * 16);

    // ---- Q fragments (bf16 hi/lo), once per block ----
    uint32_t qh[4][4], ql[4][4];
    {
        int row0 = q0 + wid*16 + r;      if (row0 >= NN) row0 = 0;
        int row1 = q0 + wid*16 + r + 8;  if (row1 >= NN) row1 = 0;
        #pragma unroll
        for (int ks = 0; ks < 4; ks++) {
            float2 v;
            v = *(const float2*)&g_q[base + row0*DD + ks*16 + 2*cg];
            split2(v.x*scale, v.y*scale, qh[ks][0], ql[ks][0]);
            v = *(const float2*)&g_q[base + row1*DD + ks*16 + 2*cg];
            split2(v.x*scale, v.y*scale, qh[ks][1], ql[ks][1]);
            v = *(const float2*)&g_q[base + row0*DD + ks*16 + 2*cg + 8];
            split2(v.x*scale, v.y*scale, qh[ks][2], ql[ks][2]);
            v = *(const float2*)&g_q[base + row1*DD + ks*16 + 2*cg + 8];
            split2(v.x*scale, v.y*scale, qh[ks][3], ql[ks][3]);
        }
    }

    float o[8][4];
    #pragma unroll
    for (int i = 0; i < 8; i++)
        #pragma unroll
        for (int j = 0; j < 4; j++) o[i][j] = 0.f;
    float lp0 = 0.f, lp1 = 0.f;

    // ---- staging: 8 x 16B cp.async per thread per tile ----
    // s=0..7: arr = s>>1 (0=Kh,1=Kl,2=Vh,3=Vl), rem = tid + 256*(s&1)
    auto issue = [&](int t0, int b) {
        uint32_t dstb = smem_u + (uint32_t)(b*4*REGU*4);
        #pragma unroll
        for (int s = 0; s < 8; s++) {
            const int arr = s >> 1;
            const int rem = tid + 256*(s & 1);
            const int c   = rem >> 3;
            const int dq  = rem & 7;
            int gr = t0 + c; if (gr >= NN) gr = NN - 1;
            const uint16_t* src =
                (arr == 0) ? g_kh : (arr == 1) ? g_kl : (arr == 2) ? g_vh : g_vl;
            cp16(dstb + (uint32_t)(arr*REGU*4 + c*144 + dq*16),
                 src + (size_t)(base + gr*DD) + dq*8, true);
        }
        asm volatile("cp.async.commit_group;");
    };

    issue(0, 0);

    int it = 0;
    for (int t0 = 0; t0 < NN; t0 += 64, it++) {
        const int b = it & 1;
        const uint32_t boff = (uint32_t)(b*4*REGU*4);
        asm volatile("cp.async.wait_group 0;");
        __syncthreads();           // publishes buf b; fences reuse of buf b^1
        if (t0 + 64 < NN) issue(t0 + 64, b ^ 1);

        const uint32_t kh_u = smem_u + boff;
        const uint32_t kl_u = kh_u + REGU*4;
        const uint32_t vh_u = kl_u + REGU*4;
        const uint32_t vl_u = vh_u + REGU*4;

        float p[8][4];
        #pragma unroll
        for (int nt = 0; nt < 8; nt++)
            #pragma unroll
            for (int j = 0; j < 4; j++) p[nt][j] = 0.f;

        // ---- QK (K frags via non-trans ldmatrix.x4) ----
        #pragma unroll
        for (int ntp = 0; ntp < 4; ntp++) {
            #pragma unroll
            for (int ks = 0; ks < 4; ks++) {
                uint32_t off = (uint32_t)(ntp*16*(AT_STR*4) + ks*32) + lrow;
                uint32_t bh0, bh1, bh2, bh3, bl0, bl1, bl2, bl3;
                ldsm4(bh0, bh1, bh2, bh3, kh_u + off);
                ldsm4(bl0, bl1, bl2, bl3, kl_u + off);
                mma_bf16(p[2*ntp],   qh[ks], bh0, bh1);
                mma_bf16(p[2*ntp],   qh[ks], bl0, bl1);
                mma_bf16(p[2*ntp],   ql[ks], bh0, bh1);
                mma_bf16(p[2*ntp+1], qh[ks], bh2, bh3);
                mma_bf16(p[2*ntp+1], qh[ks], bl2, bl3);
                mma_bf16(p[2*ntp+1], ql[ks], bh2, bh3);
            }
        }

        // ---- exp (max-free) + mask + row sums ----
        #pragma unroll
        for (int nt = 0; nt < 8; nt++) {
            int c01 = t0 + nt*8 + 2*cg;
            p[nt][0] = (c01     < NN) ? __expf(p[nt][0]) : 0.f;
            p[nt][1] = (c01 + 1 < NN) ? __expf(p[nt][1]) : 0.f;
            p[nt][2] = (c01     < NN) ? __expf(p[nt][2]) : 0.f;
            p[nt][3] = (c01 + 1 < NN) ? __expf(p[nt][3]) : 0.f;
            lp0 += p[nt][0] + p[nt][1];
            lp1 += p[nt][2] + p[nt][3];
        }

        // ---- PV (P in registers, V frags via trans ldmatrix.x4) ----
        #pragma unroll
        for (int ks = 0; ks < 4; ks++) {
            uint32_t ah[4], al[4];
            split2(p[2*ks  ][0], p[2*ks  ][1], ah[0], al[0]);
            split2(p[2*ks  ][2], p[2*ks  ][3], ah[1], al[1]);
            split2(p[2*ks+1][0], p[2*ks+1][1], ah[2], al[2]);
            split2(p[2*ks+1][2], p[2*ks+1][3], ah[3], al[3]);
            #pragma unroll
            for (int dtp = 0; dtp < 4; dtp++) {
                uint32_t off = (uint32_t)((16*ks + crow)*(AT_STR*4) + (dtp*16 + dcol)*2);
                uint32_t h0, h1, h2, h3, l0, l1, l2, l3;
                ldsm4t(h0, h1, h2, h3, vh_u + off);
                ldsm4t(l0, l1, l2, l3, vl_u + off);
                mma_bf16(o[2*dtp],   ah, h0, h1);
                mma_bf16(o[2*dtp],   ah, l0, l1);
                mma_bf16(o[2*dtp],   al, h0, h1);
                mma_bf16(o[2*dtp+1], ah, h2, h3);
                mma_bf16(o[2*dtp+1], ah, l2, l3);
                mma_bf16(o[2*dtp+1], al, h2, h3);
            }
        }
    }

    lp0 += __shfl_xor_sync(0xffffffffu, lp0, 1);
    lp0 += __shfl_xor_sync(0xffffffffu, lp0, 2);
    lp1 += __shfl_xor_sync(0xffffffffu, lp1, 1);
    lp1 += __shfl_xor_sync(0xffffffffu, lp1, 2);
    const float inv0 = 1.f / lp0;
    const float inv1 = 1.f / lp1;

    const int b = bh / HH, h = bh % HH;
    const int grow0 = q0 + wid*16 + r;
    const int grow1 = grow0 + 8;
    #pragma unroll
    for (int dt = 0; dt < 8; dt++) {
        int d = dt*8 + 2*cg;
        if (grow0 < NN)
            *(float2*)&g_o[((size_t)(b*NN + grow0))*CC + h*DD + d] =
                make_float2(to_tf32(o[dt][0]*inv0), to_tf32(o[dt][1]*inv0));
        if (grow1 < NN)
            *(float2*)&g_o[((size_t)(b*NN + grow1))*CC + h*DD + d] =
                make_float2(to_tf32(o[dt][2]*inv1), to_tf32(o[dt][3]*inv1));
    }
}

// ---------------- launch ----------------
extern "C" void kernel_launch(void* const* d_in, const int* in_sizes, int n_in,
                              void* d_out, int out_size)
{
    const float* x      = (const float*)d_in[0];
    const float* rope   = (const float*)d_in[1];
    const float* qkv_w  = (const float*)d_in[2];
    const float* q_bias = (const float*)d_in[3];
    const float* v_bias = (const float*)d_in[4];
    const float* proj_w = (const float*)d_in[5];
    const float* proj_b = (const float*)d_in[6];
    float* out = (float*)d_out;

    cudaFuncSetAttribute(attn_mma_kernel,
                         cudaFuncAttributeMaxDynamicSharedMemorySize, ATTN4_SMEM);
    cudaFuncSetAttribute(mma_gemm<0>,
                         cudaFuncAttributeMaxDynamicSharedMemorySize, GEMM_SMEM);
    cudaFuncSetAttribute(mma_gemm<1>,
                         cudaFuncAttributeMaxDynamicSharedMemorySize, GEMM_SMEM);

    float *xr, *wq, *wp, *gk, *gv, *go;
    uint16_t *kh, *kl, *vh, *vl;
    cudaGetSymbolAddress((void**)&xr, g_xr);
    cudaGetSymbolAddress((void**)&wq, g_wq);
    cudaGetSymbolAddress((void**)&wp, g_wp);
    cudaGetSymbolAddress((void**)&gk, g_k);
    cudaGetSymbolAddress((void**)&gv, g_v);
    cudaGetSymbolAddress((void**)&go, g_o);
    cudaGetSymbolAddress((void**)&kh, g_kh);
    cudaGetSymbolAddress((void**)&kl, g_kl);
    cudaGetSymbolAddress((void**)&vh, g_vh);
    cudaGetSymbolAddress((void**)&vl, g_vl);

    // 0. pre-round GEMM operands to tf32
    cvt_tf32_kernel<<<(MM*KDIM/4 + 255)/256, 256>>>(x, xr, MM*KDIM/4);
    cvt_tf32_kernel<<<(QKV_N*KDIM/4 + 255)/256, 256>>>(qkv_w, wq, QKV_N*KDIM/4);
    cvt_tf32_kernel<<<(CC*KDIM/4 + 255)/256, 256>>>(proj_w, wp, CC*KDIM/4);

    const int MB = (MM + 127) / 128;

    // 1. QKV GEMM -> g_q, g_k, g_v
    mma_gemm<0><<<dim3(QKV_N/128, MB), 256, GEMM_SMEM>>>(xr, wq, q_bias, v_bias, nullptr);

    // 2. RoPE (q, k in place)
    int rtot = BB*HH*(NN-1)*(DD/2);
    rope_kernel<<<(rtot + 255)/256, 256>>>(rope);

    // 2b. split K (post-RoPE) and V to bf16 hi/lo
    const int kvn4 = BB*HH*NN*DD/4;
    cvt_bf16_kernel<<<(kvn4 + 255)/256, 256>>>(gk, kh, kl, kvn4);
    cvt_bf16_kernel<<<(kvn4 + 255)/256, 256>>>(gv, vh, vl, kvn4);

    // 3. attention -> g_o (tf32-rounded)
    attn_mma_kernel<<<dim3((NN + 127)/128, BB*HH), 256, ATTN4_SMEM>>>();

    // 4. output projection -> d_out
    mma_gemm<1><<<dim3(CC/128, MB), 256, GEMM_SMEM>>>(go, wp, proj_b, nullptr, out);
}

// round 15
// speedup vs baseline: 1.1453x; 1.1453x over previous
#include <cuda_runtime.h>
#include <stdint.h>
#include <math.h>

#define BB 32
#define NN 577
#define CC 768
#define HH 12
#define DD 64
#define MM (BB*NN)      // 18464
#define KDIM 768
#define QKV_N 2304

// ---------------- scratch ----------------
__device__ float g_q[BB*HH*NN*DD];   // [B,H,N,D]
__device__ float g_k[BB*HH*NN*DD];
__device__ float g_v[BB*HH*NN*DD];
__device__ float g_o[MM*CC];         // attention output (tf32-rounded), [B*N, C]
__device__ float g_xr[MM*KDIM];      // x, tf32-rounded
__device__ float g_wq[QKV_N*KDIM];   // qkv_w, tf32-rounded
__device__ float g_wp[CC*KDIM];      // proj_w, tf32-rounded

__device__ __forceinline__ float to_tf32(float x) {
    uint32_t u;
    asm("cvt.rna.tf32.f32 %0, %1;" : "=r"(u) : "f"(x));
    return __uint_as_float(u);
}

// bf16 helpers — fast RNE pack via cvt.rn.bf16x2 (bit-identical to manual RNE)
__device__ __forceinline__ uint32_t pack2(float a, float b) {
    uint32_t d;   // low half = a, high half = b
    asm("cvt.rn.bf16x2.f32 %0, %1, %2;" : "=r"(d) : "f"(b), "f"(a));
    return d;
}
__device__ __forceinline__ void split2(float a, float b, uint32_t& hi, uint32_t& lo) {
    hi = pack2(a, b);
    float r0 = a - __uint_as_float(hi << 16);
    float r1 = b - __uint_as_float(hi & 0xFFFF0000u);
    lo = pack2(r0, r1);
}

__device__ __forceinline__ void mma_bf16(float* c, const uint32_t* a, uint32_t b0, uint32_t b1) {
    asm volatile(
        "mma.sync.aligned.m16n8k16.row.col.f32.bf16.bf16.f32 "
        "{%0,%1,%2,%3},{%4,%5,%6,%7},{%8,%9},{%0,%1,%2,%3};"
        : "+f"(c[0]), "+f"(c[1]), "+f"(c[2]), "+f"(c[3])
        : "r"(a[0]), "r"(a[1]), "r"(a[2]), "r"(a[3]), "r"(b0), "r"(b1));
}

__device__ __forceinline__ void ldsm4t(uint32_t& a, uint32_t& b, uint32_t& c, uint32_t& d,
                                       uint32_t addr) {
    asm volatile("ldmatrix.sync.aligned.m8n8.x4.trans.shared.b16 {%0,%1,%2,%3}, [%4];"
        : "=r"(a), "=r"(b), "=r"(c), "=r"(d) : "r"(addr));
}

__device__ __forceinline__ void ldsm4(uint32_t& a, uint32_t& b, uint32_t& c, uint32_t& d,
                                      uint32_t addr) {
    asm volatile("ldmatrix.sync.aligned.m8n8.x4.shared.b16 {%0,%1,%2,%3}, [%4];"
        : "=r"(a), "=r"(b), "=r"(c), "=r"(d) : "r"(addr));
}

__device__ __forceinline__ void cp16(uint32_t dst, const void* src, bool pred) {
    int sz = pred ? 16 : 0;
    asm volatile("cp.async.cg.shared.global [%0], [%1], 16, %2;"
                 :: "r"(dst), "l"(src), "r"(sz));
}

// ---------------- tf32 conversion (elementwise, float4) ----------------
__global__ void cvt_tf32_kernel(const float* __restrict__ in, float* __restrict__ out, int n4)
{
    int i = blockIdx.x * blockDim.x + threadIdx.x;
    if (i < n4) {
        float4 v = ((const float4*)in)[i];
        v.x = to_tf32(v.x); v.y = to_tf32(v.y);
        v.z = to_tf32(v.z); v.w = to_tf32(v.w);
        ((float4*)out)[i] = v;
    }
}

// ---------------- tf32 GEMM, 2-stage cp.async (round-12, proven) ----------
#define GEMM_SMEM (4 * 128 * 32 * 4)   // 65536 B

template<int MODE>
__global__ __launch_bounds__(256) void mma_gemm(
    const float* __restrict__ Aop, const float* __restrict__ Wop,
    const float* __restrict__ bias_q, const float* __restrict__ bias_v,
    float* __restrict__ out)
{
    extern __shared__ float smg[];
    float* As = smg;                // [2][128*32]
    float* Bs = smg + 2*128*32;

    const int tid  = threadIdx.x;
    const int lane = tid & 31;
    const int warp = tid >> 5;
    const int wm   = (warp >> 2) * 64;
    const int wn   = (warp & 3) * 32;
    const int r    = lane >> 2;
    const int cg   = lane & 3;

    const int m0 = blockIdx.y * 128;
    const int n0 = blockIdx.x * 128;

    uint32_t asu = (uint32_t)__cvta_generic_to_shared(As);
    uint32_t bsu = (uint32_t)__cvta_generic_to_shared(Bs);

    const int srow = tid >> 3;
    const int sg   = tid & 7;

    float acc[4][4][4];
    #pragma unroll
    for (int i = 0; i < 4; i++)
        #pragma unroll
        for (int j = 0; j < 4; j++)
            #pragma unroll
            for (int q = 0; q < 4; q++) acc[i][j][q] = 0.f;

    const int NK = KDIM / 32;   // 24

    auto issue = [&](int kt, int s) {
        int k0 = kt * 32;
        #pragma unroll
        for (int i = 0; i < 4; i++) {
            int row = srow + 32*i;
            int sw  = ((sg ^ (row & 7)) << 2);
            uint32_t off = (uint32_t)((s*4096 + row*32 + sw) << 2);
            cp16(asu + off, &Aop[(size_t)(m0+row)*KDIM + k0 + sg*4], (m0+row) < MM);
            cp16(bsu + off, &Wop[(size_t)(n0+row)*KDIM + k0 + sg*4], true);
        }
        asm volatile("cp.async.commit_group;");
    };

    issue(0, 0);

    for (int kt = 0; kt < NK; kt++) {
        const int s = kt & 1;
        asm volatile("cp.async.wait_group 0;");
        __syncthreads();
        if (kt + 1 < NK) issue(kt + 1, s ^ 1);

        const float* Ab = As + s*4096;
        const float* Bb = Bs + s*4096;

        #pragma unroll
        for (int kk = 0; kk < 32; kk += 8) {
            const int g0 = kk >> 2;
            const int c0 = ((g0 ^ r) << 2) + cg;
            const int c1 = (((g0 + 1) ^ r) << 2) + cg;
            uint32_t af[4][4], bf[4][2];
            #pragma unroll
            for (int mt = 0; mt < 4; mt++) {
                const float* p = &Ab[(wm + mt*16 + r)*32];
                af[mt][0] = __float_as_uint(p[c0]);
                af[mt][1] = __float_as_uint(p[8*32 + c0]);
                af[mt][2] = __float_as_uint(p[c1]);
                af[mt][3] = __float_as_uint(p[8*32 + c1]);
            }
            #pragma unroll
            for (int nt = 0; nt < 4; nt++) {
                const float* p = &Bb[(wn + nt*8 + r)*32];
                bf[nt][0] = __float_as_uint(p[c0]);
                bf[nt][1] = __float_as_uint(p[c1]);
            }
            #pragma unroll
            for (int mt = 0; mt < 4; mt++)
                #pragma unroll
                for (int nt = 0; nt < 4; nt++) {
                    asm volatile(
                        "mma.sync.aligned.m16n8k8.row.col.f32.tf32.tf32.f32 "
                        "{%0,%1,%2,%3},{%4,%5,%6,%7},{%8,%9},{%0,%1,%2,%3};"
                        : "+f"(acc[mt][nt][0]), "+f"(acc[mt][nt][1]),
                          "+f"(acc[mt][nt][2]), "+f"(acc[mt][nt][3])
                        : "r"(af[mt][0]), "r"(af[mt][1]),
                          "r"(af[mt][2]), "r"(af[mt][3]),
                          "r"(bf[nt][0]), "r"(bf[nt][1]));
                }
        }
    }

    // ---------------- epilogue ----------------
    #pragma unroll
    for (int nt = 0; nt < 4; nt++) {
        int col = n0 + wn + nt*8 + 2*cg;
        if (MODE == 0) {
            int which = col / CC;
            int rem   = col - which*CC;
            int h     = rem >> 6;
            int d     = rem & 63;
            float b0 = (which == 0) ? bias_q[rem]   : (which == 2) ? bias_v[rem]   : 0.f;
            float b1 = (which == 0) ? bias_q[rem+1] : (which == 2) ? bias_v[rem+1] : 0.f;
            float* dst = (which == 0) ? g_q : (which == 1) ? g_k : g_v;
            #pragma unroll
            for (int mt = 0; mt < 4; mt++) {
                #pragma unroll
                for (int half = 0; half < 2; half++) {
                    int m = m0 + wm + mt*16 + r + half*8;
                    if (m < MM) {
                        int bb = m / NN, n = m - bb*NN;
                        float2 v = make_float2(acc[mt][nt][half*2]   + b0,
                                               acc[mt][nt][half*2+1] + b1);
                        *(float2*)&dst[(((size_t)bb*HH + h)*NN + n)*DD + d] = v;
                    }
                }
            }
        } else {
            float b0 = bias_q[col], b1 = bias_q[col+1];
            #pragma unroll
            for (int mt = 0; mt < 4; mt++) {
                #pragma unroll
                for (int half = 0; half < 2; half++) {
                    int m = m0 + wm + mt*16 + r + half*8;
                    if (m < MM) {
                        float2 v = make_float2(acc[mt][nt][half*2]   + b0,
                                               acc[mt][nt][half*2+1] + b1);
                        *(float2*)&out[(size_t)m*CC + col] = v;
                    }
                }
            }
        }
    }
}

// ---------------- RoPE ----------------
__global__ void rope_kernel(const float* __restrict__ rope)
{
    int idx = blockIdx.x * blockDim.x + threadIdx.x;
    const int total = BB*HH*(NN-1)*(DD/2);
    if (idx >= total) return;
    int pair = idx & 31;
    int rest = idx >> 5;
    int nr = rest % (NN-1);
    int bh = rest / (NN-1);
    int d0 = pair * 2;

    float s0 = rope[nr*2*DD + d0];
    float s1 = rope[nr*2*DD + d0 + 1];
    float c0 = rope[nr*2*DD + DD + d0];
    float c1 = rope[nr*2*DD + DD + d0 + 1];

    int base = (bh*NN + (nr + 1))*DD + d0;
    float2 q = *(float2*)&g_q[base];
    float2 k = *(float2*)&g_k[base];
    *(float2*)&g_q[base] = make_float2(q.x*c0 - q.y*s0, q.y*c1 + q.x*s1);
    *(float2*)&g_k[base] = make_float2(k.x*c0 - k.y*s0, k.y*c1 + k.x*s1);
}

// ---------------- Tensor-core flash attention (round-12 + fast split2 + tail split)
#define AT_STR 36
#define ATTN3_SMEM (4*64*AT_STR*4)

__global__ __launch_bounds__(256) void attn_mma_kernel()
{
    extern __shared__ uint32_t smu[];
    uint32_t* Kh = smu;
    uint32_t* Kl = Kh + 64*AT_STR;
    uint32_t* Vh = Kl + 64*AT_STR;
    uint32_t* Vl = Vh + 64*AT_STR;

    const int tid  = threadIdx.x;
    const int lane = tid & 31;
    const int wid  = tid >> 5;
    const int r    = lane >> 2;
    const int cg   = lane & 3;

    const int bh   = blockIdx.y;
    const int q0   = blockIdx.x * 128;
    const int base = bh * NN * DD;
    const float scale = 0.125f;

    const uint32_t kh_u = (uint32_t)__cvta_generic_to_shared(Kh);
    const uint32_t kl_u = (uint32_t)__cvta_generic_to_shared(Kl);
    const uint32_t vh_u = (uint32_t)__cvta_generic_to_shared(Vh);
    const uint32_t vl_u = (uint32_t)__cvta_generic_to_shared(Vl);
    // trans-ldmatrix lane addressing (V)
    const int crow = ((lane >> 3) & 1) * 8 + (lane & 7);
    const int dcol = (lane >> 4) * 8;
    // non-trans ldmatrix lane addressing (K)
    const uint32_t lrow = (uint32_t)((((lane >> 4)*8 + (lane & 7)) * (AT_STR*4))
                                     + ((lane >> 3) & 1) * 16);

    uint32_t qh[4][4], ql[4][4];
    {
        int row0 = q0 + wid*16 + r;      if (row0 >= NN) row0 = 0;
        int row1 = q0 + wid*16 + r + 8;  if (row1 >= NN) row1 = 0;
        #pragma unroll
        for (int ks = 0; ks < 4; ks++) {
            float2 v;
            v = *(const float2*)&g_q[base + row0*DD + ks*16 + 2*cg];
            split2(v.x*scale, v.y*scale, qh[ks][0], ql[ks][0]);
            v = *(const float2*)&g_q[base + row1*DD + ks*16 + 2*cg];
            split2(v.x*scale, v.y*scale, qh[ks][1], ql[ks][1]);
            v = *(const float2*)&g_q[base + row0*DD + ks*16 + 2*cg + 8];
            split2(v.x*scale, v.y*scale, qh[ks][2], ql[ks][2]);
            v = *(const float2*)&g_q[base + row1*DD + ks*16 + 2*cg + 8];
            split2(v.x*scale, v.y*scale, qh[ks][3], ql[ks][3]);
        }
    }

    float o[8][4];
    #pragma unroll
    for (int i = 0; i < 8; i++)
        #pragma unroll
        for (int j = 0; j < 4; j++) o[i][j] = 0.f;
    float lp0 = 0.f, lp1 = 0.f;

    float4 pk[4], pv[4];
    auto prefetch = [&](int t0) {
        #pragma unroll
        for (int s = 0; s < 4; s++) {
            int f4 = tid + 256*s;
            int c  = f4 >> 4;
            int dq = f4 & 15;
            int gr = t0 + c; if (gr >= NN) gr = NN - 1;
            pk[s] = *(const float4*)&g_k[base + gr*DD + dq*4];
            pv[s] = *(const float4*)&g_v[base + gr*DD + dq*4];
        }
    };
    prefetch(0);

    for (int t0 = 0; t0 < NN; t0 += 64) {
        __syncthreads();

        #pragma unroll
        for (int s = 0; s < 4; s++) {
            int f4 = tid + 256*s;
            int c  = f4 >> 4;
            int dq = f4 & 15;
            uint32_t h0, l0, h1, l1;
            split2(pk[s].x, pk[s].y, h0, l0); split2(pk[s].z, pk[s].w, h1, l1);
            *(uint2*)&Kh[c*AT_STR + dq*2] = make_uint2(h0, h1);
            *(uint2*)&Kl[c*AT_STR + dq*2] = make_uint2(l0, l1);
            split2(pv[s].x, pv[s].y, h0, l0); split2(pv[s].z, pv[s].w, h1, l1);
            *(uint2*)&Vh[c*AT_STR + dq*2] = make_uint2(h0, h1);
            *(uint2*)&Vl[c*AT_STR + dq*2] = make_uint2(l0, l1);
        }
        __syncthreads();

        if (t0 + 64 < NN) prefetch(t0 + 64);

        float p[8][4];
        #pragma unroll
        for (int nt = 0; nt < 8; nt++)
            #pragma unroll
            for (int j = 0; j < 4; j++) p[nt][j] = 0.f;

        // ---- QK: K fragments via non-trans ldmatrix.x4 ----
        #pragma unroll
        for (int ntp = 0; ntp < 4; ntp++) {
            #pragma unroll
            for (int ks = 0; ks < 4; ks++) {
                uint32_t off = (uint32_t)(ntp*16*(AT_STR*4) + ks*32) + lrow;
                uint32_t bh0, bh1, bh2, bh3, bl0, bl1, bl2, bl3;
                ldsm4(bh0, bh1, bh2, bh3, kh_u + off);
                ldsm4(bl0, bl1, bl2, bl3, kl_u + off);
                mma_bf16(p[2*ntp],   qh[ks], bh0, bh1);
                mma_bf16(p[2*ntp],   qh[ks], bl0, bl1);
                mma_bf16(p[2*ntp],   ql[ks], bh0, bh1);
                mma_bf16(p[2*ntp+1], qh[ks], bh2, bh3);
                mma_bf16(p[2*ntp+1], qh[ks], bl2, bl3);
                mma_bf16(p[2*ntp+1], ql[ks], bh2, bh3);
            }
        }

        // ---- exp (max-free): fast path for full tiles, mask only on tail ----
        if (t0 + 64 <= NN) {
            #pragma unroll
            for (int nt = 0; nt < 8; nt++) {
                p[nt][0] = __expf(p[nt][0]);
                p[nt][1] = __expf(p[nt][1]);
                p[nt][2] = __expf(p[nt][2]);
                p[nt][3] = __expf(p[nt][3]);
                lp0 += p[nt][0] + p[nt][1];
                lp1 += p[nt][2] + p[nt][3];
            }
        } else {
            #pragma unroll
            for (int nt = 0; nt < 8; nt++) {
                int c01 = t0 + nt*8 + 2*cg;
                p[nt][0] = (c01     < NN) ? __expf(p[nt][0]) : 0.f;
                p[nt][1] = (c01 + 1 < NN) ? __expf(p[nt][1]) : 0.f;
                p[nt][2] = (c01     < NN) ? __expf(p[nt][2]) : 0.f;
                p[nt][3] = (c01 + 1 < NN) ? __expf(p[nt][3]) : 0.f;
                lp0 += p[nt][0] + p[nt][1];
                lp1 += p[nt][2] + p[nt][3];
            }
        }

        // ---- PV (P in registers, V frags via trans ldmatrix.x4) ----
        #pragma unroll
        for (int ks = 0; ks < 4; ks++) {
            uint32_t ah[4], al[4];
            split2(p[2*ks  ][0], p[2*ks  ][1], ah[0], al[0]);
            split2(p[2*ks  ][2], p[2*ks  ][3], ah[1], al[1]);
            split2(p[2*ks+1][0], p[2*ks+1][1], ah[2], al[2]);
            split2(p[2*ks+1][2], p[2*ks+1][3], ah[3], al[3]);
            #pragma unroll
            for (int dtp = 0; dtp < 4; dtp++) {
                uint32_t off = (uint32_t)((((16*ks + crow)*2*AT_STR) + dtp*16 + dcol) << 1);
                uint32_t h0, h1, h2, h3, l0, l1, l2, l3;
                ldsm4t(h0, h1, h2, h3, vh_u + off);
                ldsm4t(l0, l1, l2, l3, vl_u + off);
                mma_bf16(o[2*dtp],   ah, h0, h1);
                mma_bf16(o[2*dtp],   ah, l0, l1);
                mma_bf16(o[2*dtp],   al, h0, h1);
                mma_bf16(o[2*dtp+1], ah, h2, h3);
                mma_bf16(o[2*dtp+1], ah, l2, l3);
                mma_bf16(o[2*dtp+1], al, h2, h3);
            }
        }
    }

    lp0 += __shfl_xor_sync(0xffffffffu, lp0, 1);
    lp0 += __shfl_xor_sync(0xffffffffu, lp0, 2);
    lp1 += __shfl_xor_sync(0xffffffffu, lp1, 1);
    lp1 += __shfl_xor_sync(0xffffffffu, lp1, 2);
    const float inv0 = 1.f / lp0;
    const float inv1 = 1.f / lp1;

    const int b = bh / HH, h = bh % HH;
    const int grow0 = q0 + wid*16 + r;
    const int grow1 = grow0 + 8;
    #pragma unroll
    for (int dt = 0; dt < 8; dt++) {
        int d = dt*8 + 2*cg;
        if (grow0 < NN)
            *(float2*)&g_o[((size_t)(b*NN + grow0))*CC + h*DD + d] =
                make_float2(to_tf32(o[dt][0]*inv0), to_tf32(o[dt][1]*inv0));
        if (grow1 < NN)
            *(float2*)&g_o[((size_t)(b*NN + grow1))*CC + h*DD + d] =
                make_float2(to_tf32(o[dt][2]*inv1), to_tf32(o[dt][3]*inv1));
    }
}

// ---------------- launch ----------------
extern "C" void kernel_launch(void* const* d_in, const int* in_sizes, int n_in,
                              void* d_out, int out_size)
{
    const float* x      = (const float*)d_in[0];
    const float* rope   = (const float*)d_in[1];
    const float* qkv_w  = (const float*)d_in[2];
    const float* q_bias = (const float*)d_in[3];
    const float* v_bias = (const float*)d_in[4];
    const float* proj_w = (const float*)d_in[5];
    const float* proj_b = (const float*)d_in[6];
    float* out = (float*)d_out;

    cudaFuncSetAttribute(attn_mma_kernel,
                         cudaFuncAttributeMaxDynamicSharedMemorySize, ATTN3_SMEM);
    cudaFuncSetAttribute(mma_gemm<0>,
                         cudaFuncAttributeMaxDynamicSharedMemorySize, GEMM_SMEM);
    cudaFuncSetAttribute(mma_gemm<1>,
                         cudaFuncAttributeMaxDynamicSharedMemorySize, GEMM_SMEM);

    float *xr, *wq, *wp, *go;
    cudaGetSymbolAddress((void**)&xr, g_xr);
    cudaGetSymbolAddress((void**)&wq, g_wq);
    cudaGetSymbolAddress((void**)&wp, g_wp);
    cudaGetSymbolAddress((void**)&go, g_o);

    // 0. pre-round GEMM operands to tf32
    cvt_tf32_kernel<<<(MM*KDIM/4 + 255)/256, 256>>>(x, xr, MM*KDIM/4);
    cvt_tf32_kernel<<<(QKV_N*KDIM/4 + 255)/256, 256>>>(qkv_w, wq, QKV_N*KDIM/4);
    cvt_tf32_kernel<<<(CC*KDIM/4 + 255)/256, 256>>>(proj_w, wp, CC*KDIM/4);

    const int MB = (MM + 127) / 128;

    // 1. QKV GEMM -> g_q, g_k, g_v
    mma_gemm<0><<<dim3(QKV_N/128, MB), 256, GEMM_SMEM>>>(xr, wq, q_bias, v_bias, nullptr);

    // 2. RoPE (q, k in place)
    int rtot = BB*HH*(NN-1)*(DD/2);
    rope_kernel<<<(rtot + 255)/256, 256>>>(rope);

    // 3. attention -> g_o (tf32-rounded); 128 q-rows per block
    attn_mma_kernel<<<dim3((NN + 127)/128, BB*HH), 256, ATTN3_SMEM>>>();

    // 4. output projection -> d_out
    mma_gemm<1><<<dim3(CC/128, MB), 256, GEMM_SMEM>>>(go, wp, proj_b, nullptr, out);
}